// round 1
// baseline (speedup 1.0000x reference)
#include <cuda_runtime.h>
#include <math.h>

// Problem constants (fixed by the reference: B,H,L,D = 4,8,2048,64; FACTOR=5)
#define Bq   4
#define Hq   8
#define Lq   2048
#define Dq   64
#define BH   (Bq*Hq)
#define SK   40      // sample_k = min(5*ceil(ln 2048), 2048) = 40
#define NT   40      // n_top  = 40
#define NCH  32      // cumsum chunks
#define CHLEN (Lq/NCH)

// Scratch (no allocations allowed -> device globals)
__device__ float g_M[BH*Lq];        // 256 KB
__device__ int   g_top[BH*NT];      // 5 KB
__device__ float g_ctx[BH*NT*Dq];   // 327 KB
__device__ float g_csum[BH*NCH*Dq]; // 256 KB

// ---------------------------------------------------------------------------
// Kernel 1: M[b,h,l] = max_s(q_l . k_{idx[l,s]}) - sum_s(...)/L
// warp per query row; key-row loads are 2x128B coalesced within the warp.
// ---------------------------------------------------------------------------
__global__ void k_M(const float* __restrict__ Q, const float* __restrict__ K,
                    const int* __restrict__ idxs) {
    int bh   = blockIdx.x;
    int warp = threadIdx.x >> 5;
    int lane = threadIdx.x & 31;
    int l    = blockIdx.y * 8 + warp;

    const float* q  = Q + ((size_t)bh*Lq + l)*Dq;
    float q0 = q[lane], q1 = q[lane + 32];
    const float* Kb = K + (size_t)bh*Lq*Dq;
    const int* row  = idxs + l*SK;

    float mx = -INFINITY, sm = 0.f;
    #pragma unroll 4
    for (int s = 0; s < SK; ++s) {
        int j = row[s];                       // uniform per warp -> broadcast
        const float* k = Kb + (size_t)j*Dq;
        float p = q0*k[lane] + q1*k[lane+32];
        #pragma unroll
        for (int o = 16; o; o >>= 1) p += __shfl_xor_sync(0xFFFFFFFFu, p, o);
        mx = fmaxf(mx, p);
        sm += p;
    }
    if (lane == 0) g_M[bh*Lq + l] = mx - sm * (1.0f/(float)Lq);
}

// ---------------------------------------------------------------------------
// Kernel 2: top-40 indices per (b,h) via 40x block argmax on smem copy.
// Tie-break: lower index wins (matches stable top_k).
// ---------------------------------------------------------------------------
__global__ void k_topk() {
    int bh = blockIdx.x;
    __shared__ float smv[Lq];
    __shared__ float rv[256];
    __shared__ int   ri[256];
    int tid = threadIdx.x;

    for (int i = tid; i < Lq; i += 256) smv[i] = g_M[bh*Lq + i];
    __syncthreads();

    for (int t = 0; t < NT; ++t) {
        float bv = -INFINITY; int bi = Lq;
        for (int i = tid; i < Lq; i += 256) {
            float v = smv[i];
            if (v > bv || (v == bv && i < bi)) { bv = v; bi = i; }
        }
        rv[tid] = bv; ri[tid] = bi;
        __syncthreads();
        for (int s = 128; s; s >>= 1) {
            if (tid < s) {
                float ov = rv[tid+s]; int oi = ri[tid+s];
                if (ov > rv[tid] || (ov == rv[tid] && oi < ri[tid])) {
                    rv[tid] = ov; ri[tid] = oi;
                }
            }
            __syncthreads();
        }
        if (tid == 0) { g_top[bh*NT + t] = ri[0]; smv[ri[0]] = -INFINITY; }
        __syncthreads();
    }
}

// ---------------------------------------------------------------------------
// Kernel 3: causal softmax attention for the 40 selected queries.
// Block per (b,h,u). Scores row kept in smem (<= 8KB).
// ---------------------------------------------------------------------------
__global__ void k_attn(const float* __restrict__ Q, const float* __restrict__ K,
                       const float* __restrict__ V) {
    __shared__ float qs[Dq];
    __shared__ float sc[Lq];
    __shared__ float red[8];
    __shared__ float dred[256];
    __shared__ float acc4[4][Dq];

    int bh = blockIdx.x, u = blockIdx.y;
    int tid = threadIdx.x, warp = tid >> 5, lane = tid & 31;
    int m = g_top[bh*NT + u];          // attend keys [0..m]

    const float* q = Q + ((size_t)bh*Lq + m)*Dq;
    if (tid < Dq) qs[tid] = q[tid];
    __syncthreads();

    const float* Kb = K + (size_t)bh*Lq*Dq;
    float q0 = qs[lane], q1 = qs[lane+32];

    // Phase 1: scores (scaled), per-warp running max
    float wmax = -INFINITY;
    for (int j = warp; j <= m; j += 8) {
        const float* k = Kb + (size_t)j*Dq;
        float p = q0*k[lane] + q1*k[lane+32];
        #pragma unroll
        for (int o = 16; o; o >>= 1) p += __shfl_xor_sync(0xFFFFFFFFu, p, o);
        p *= 0.125f;                   // 1/sqrt(64)
        if (lane == 0) sc[j] = p;
        wmax = fmaxf(wmax, p);
    }
    if (lane == 0) red[warp] = wmax;
    __syncthreads();

    float smax = red[0];
    #pragma unroll
    for (int w = 1; w < 8; ++w) smax = fmaxf(smax, red[w]);

    // Phase 2: exponentiate + denominator
    float dsum = 0.f;
    for (int j = tid; j <= m; j += 256) {
        float e = expf(sc[j] - smax);
        sc[j] = e;
        dsum += e;
    }
    dred[tid] = dsum;
    __syncthreads();
    for (int s = 128; s; s >>= 1) {
        if (tid < s) dred[tid] += dred[tid + s];
        __syncthreads();
    }
    float denom = dred[0];

    // Phase 3: out[d] = sum_j p_j * V[j][d]; 4-way j split across thread quads
    int d = tid & 63, quad = tid >> 6;
    const float* Vb = V + (size_t)bh*Lq*Dq;
    float a = 0.f;
    for (int j = quad; j <= m; j += 4) a += sc[j] * Vb[(size_t)j*Dq + d];
    acc4[quad][d] = a;
    __syncthreads();
    if (tid < Dq) {
        float r = (acc4[0][tid] + acc4[1][tid] + acc4[2][tid] + acc4[3][tid]) / denom;
        g_ctx[(bh*NT + u)*Dq + tid] = r;
    }
}

// ---------------------------------------------------------------------------
// Kernels 4a/4b/4c: chunked inclusive cumsum of V along L.
// ---------------------------------------------------------------------------
__global__ void k_csum1(const float* __restrict__ V) {
    int bh = blockIdx.x, ch = blockIdx.y, d = threadIdx.x;   // blockDim = 64
    const float* v = V + ((size_t)bh*Lq + ch*CHLEN)*Dq + d;
    float a = 0.f;
    #pragma unroll
    for (int l = 0; l < CHLEN; ++l) a += v[(size_t)l*Dq];
    g_csum[(bh*NCH + ch)*Dq + d] = a;
}

__global__ void k_csum2() {
    int t  = blockIdx.x*blockDim.x + threadIdx.x;            // BH*Dq = 2048
    int bh = t >> 6, d = t & 63;
    float a = 0.f;
    #pragma unroll
    for (int ch = 0; ch < NCH; ++ch) {
        int off = (bh*NCH + ch)*Dq + d;
        float s = g_csum[off];
        g_csum[off] = a;                                     // exclusive prefix
        a += s;
    }
}

__global__ void k_csum3(const float* __restrict__ V, float* __restrict__ O) {
    int bh = blockIdx.x, ch = blockIdx.y, d = threadIdx.x;   // blockDim = 64
    size_t base = ((size_t)bh*Lq + ch*CHLEN)*Dq + d;
    float a = g_csum[(bh*NCH + ch)*Dq + d];
    #pragma unroll
    for (int l = 0; l < CHLEN; ++l) {
        a += V[base + (size_t)l*Dq];
        O[base + (size_t)l*Dq] = a;
    }
}

// ---------------------------------------------------------------------------
// Kernel 5: scatter ctx_update rows into the cumsum output.
// ---------------------------------------------------------------------------
__global__ void k_scatter(float* __restrict__ O) {
    int bh = blockIdx.x;
    for (int i = threadIdx.x; i < NT*Dq; i += blockDim.x) {
        int u = i >> 6, d = i & 63;
        int row = g_top[bh*NT + u];
        O[((size_t)bh*Lq + row)*Dq + d] = g_ctx[(bh*NT + u)*Dq + d];
    }
}

extern "C" void kernel_launch(void* const* d_in, const int* in_sizes, int n_in,
                              void* d_out, int out_size) {
    const float* Q = (const float*)d_in[0];
    const float* K = (const float*)d_in[1];
    const float* V = (const float*)d_in[2];
    const int*   I = (const int*)  d_in[3];
    float* O = (float*)d_out;

    k_M      <<<dim3(BH, Lq/8), 256>>>(Q, K, I);
    k_topk   <<<BH, 256>>>();
    k_attn   <<<dim3(BH, NT), 256>>>(Q, K, V);
    k_csum1  <<<dim3(BH, NCH), 64>>>(V);
    k_csum2  <<<8, 256>>>();
    k_csum3  <<<dim3(BH, NCH), 64>>>(V, O);
    k_scatter<<<BH, 256>>>(O);
}

// round 2
// speedup vs baseline: 1.0006x; 1.0006x over previous
#include <cuda_runtime.h>
#include <math.h>

// Problem constants (fixed by the reference: B,H,L,D = 4,8,2048,64; FACTOR=5)
#define Bq   4
#define Hq   8
#define Lq   2048
#define Dq   64
#define BH   (Bq*Hq)
#define SK   40      // sample_k = min(5*ceil(ln 2048), 2048) = 40
#define NT   40      // n_top  = 40
#define NCH  32      // cumsum chunks
#define CHLEN (Lq/NCH)

// Scratch (no allocations allowed -> device globals)
__device__ float g_M[BH*Lq];        // 256 KB
__device__ int   g_top[BH*NT];      // 5 KB
__device__ float g_ctx[BH*NT*Dq];   // 327 KB
__device__ float g_csum[BH*NCH*Dq]; // 256 KB

// ---------------------------------------------------------------------------
// Kernel 1: M[b,h,l] = max_s(q_l . k_{idx[l,s]}) - sum_s(...)/L
// warp per query row; key-row loads are 2x128B coalesced within the warp.
// ---------------------------------------------------------------------------
__global__ void k_M(const float* __restrict__ Q, const float* __restrict__ K,
                    const int* __restrict__ idxs) {
    int bh   = blockIdx.x;
    int warp = threadIdx.x >> 5;
    int lane = threadIdx.x & 31;
    int l    = blockIdx.y * 8 + warp;

    const float* q  = Q + ((size_t)bh*Lq + l)*Dq;
    float q0 = q[lane], q1 = q[lane + 32];
    const float* Kb = K + (size_t)bh*Lq*Dq;
    const int* row  = idxs + l*SK;

    float mx = -INFINITY, sm = 0.f;
    #pragma unroll 4
    for (int s = 0; s < SK; ++s) {
        int j = row[s];                       // uniform per warp -> broadcast
        const float* k = Kb + (size_t)j*Dq;
        float p = q0*k[lane] + q1*k[lane+32];
        #pragma unroll
        for (int o = 16; o; o >>= 1) p += __shfl_xor_sync(0xFFFFFFFFu, p, o);
        mx = fmaxf(mx, p);
        sm += p;
    }
    if (lane == 0) g_M[bh*Lq + l] = mx - sm * (1.0f/(float)Lq);
}

// ---------------------------------------------------------------------------
// Kernel 2: top-40 indices per (b,h) via 40x block argmax on smem copy.
// Tie-break: lower index wins (matches stable top_k).
// ---------------------------------------------------------------------------
__global__ void k_topk() {
    int bh = blockIdx.x;
    __shared__ float smv[Lq];
    __shared__ float rv[256];
    __shared__ int   ri[256];
    int tid = threadIdx.x;

    for (int i = tid; i < Lq; i += 256) smv[i] = g_M[bh*Lq + i];
    __syncthreads();

    for (int t = 0; t < NT; ++t) {
        float bv = -INFINITY; int bi = Lq;
        for (int i = tid; i < Lq; i += 256) {
            float v = smv[i];
            if (v > bv || (v == bv && i < bi)) { bv = v; bi = i; }
        }
        rv[tid] = bv; ri[tid] = bi;
        __syncthreads();
        for (int s = 128; s; s >>= 1) {
            if (tid < s) {
                float ov = rv[tid+s]; int oi = ri[tid+s];
                if (ov > rv[tid] || (ov == rv[tid] && oi < ri[tid])) {
                    rv[tid] = ov; ri[tid] = oi;
                }
            }
            __syncthreads();
        }
        if (tid == 0) { g_top[bh*NT + t] = ri[0]; smv[ri[0]] = -INFINITY; }
        __syncthreads();
    }
}

// ---------------------------------------------------------------------------
// Kernel 3: causal softmax attention for the 40 selected queries.
// Block per (b,h,u). Scores row kept in smem (<= 8KB).
// ---------------------------------------------------------------------------
__global__ void k_attn(const float* __restrict__ Q, const float* __restrict__ K,
                       const float* __restrict__ V) {
    __shared__ float qs[Dq];
    __shared__ float sc[Lq];
    __shared__ float red[8];
    __shared__ float dred[256];
    __shared__ float acc4[4][Dq];

    int bh = blockIdx.x, u = blockIdx.y;
    int tid = threadIdx.x, warp = tid >> 5, lane = tid & 31;
    int m = g_top[bh*NT + u];          // attend keys [0..m]

    const float* q = Q + ((size_t)bh*Lq + m)*Dq;
    if (tid < Dq) qs[tid] = q[tid];
    __syncthreads();

    const float* Kb = K + (size_t)bh*Lq*Dq;
    float q0 = qs[lane], q1 = qs[lane+32];

    // Phase 1: scores (scaled), per-warp running max
    float wmax = -INFINITY;
    for (int j = warp; j <= m; j += 8) {
        const float* k = Kb + (size_t)j*Dq;
        float p = q0*k[lane] + q1*k[lane+32];
        #pragma unroll
        for (int o = 16; o; o >>= 1) p += __shfl_xor_sync(0xFFFFFFFFu, p, o);
        p *= 0.125f;                   // 1/sqrt(64)
        if (lane == 0) sc[j] = p;
        wmax = fmaxf(wmax, p);
    }
    if (lane == 0) red[warp] = wmax;
    __syncthreads();

    float smax = red[0];
    #pragma unroll
    for (int w = 1; w < 8; ++w) smax = fmaxf(smax, red[w]);

    // Phase 2: exponentiate + denominator
    float dsum = 0.f;
    for (int j = tid; j <= m; j += 256) {
        float e = expf(sc[j] - smax);
        sc[j] = e;
        dsum += e;
    }
    dred[tid] = dsum;
    __syncthreads();
    for (int s = 128; s; s >>= 1) {
        if (tid < s) dred[tid] += dred[tid + s];
        __syncthreads();
    }
    float denom = dred[0];

    // Phase 3: out[d] = sum_j p_j * V[j][d]; 4-way j split across thread quads
    int d = tid & 63, quad = tid >> 6;
    const float* Vb = V + (size_t)bh*Lq*Dq;
    float a = 0.f;
    for (int j = quad; j <= m; j += 4) a += sc[j] * Vb[(size_t)j*Dq + d];
    acc4[quad][d] = a;
    __syncthreads();
    if (tid < Dq) {
        float r = (acc4[0][tid] + acc4[1][tid] + acc4[2][tid] + acc4[3][tid]) / denom;
        g_ctx[(bh*NT + u)*Dq + tid] = r;
    }
}

// ---------------------------------------------------------------------------
// Kernels 4a/4b/4c: chunked inclusive cumsum of V along L.
// ---------------------------------------------------------------------------
__global__ void k_csum1(const float* __restrict__ V) {
    int bh = blockIdx.x, ch = blockIdx.y, d = threadIdx.x;   // blockDim = 64
    const float* v = V + ((size_t)bh*Lq + ch*CHLEN)*Dq + d;
    float a = 0.f;
    #pragma unroll
    for (int l = 0; l < CHLEN; ++l) a += v[(size_t)l*Dq];
    g_csum[(bh*NCH + ch)*Dq + d] = a;
}

__global__ void k_csum2() {
    int t  = blockIdx.x*blockDim.x + threadIdx.x;            // BH*Dq = 2048
    int bh = t >> 6, d = t & 63;
    float a = 0.f;
    #pragma unroll
    for (int ch = 0; ch < NCH; ++ch) {
        int off = (bh*NCH + ch)*Dq + d;
        float s = g_csum[off];
        g_csum[off] = a;                                     // exclusive prefix
        a += s;
    }
}

__global__ void k_csum3(const float* __restrict__ V, float* __restrict__ O) {
    int bh = blockIdx.x, ch = blockIdx.y, d = threadIdx.x;   // blockDim = 64
    size_t base = ((size_t)bh*Lq + ch*CHLEN)*Dq + d;
    float a = g_csum[(bh*NCH + ch)*Dq + d];
    #pragma unroll
    for (int l = 0; l < CHLEN; ++l) {
        a += V[base + (size_t)l*Dq];
        O[base + (size_t)l*Dq] = a;
    }
}

// ---------------------------------------------------------------------------
// Kernel 5: scatter ctx_update rows into the cumsum output.
// ---------------------------------------------------------------------------
__global__ void k_scatter(float* __restrict__ O) {
    int bh = blockIdx.x;
    for (int i = threadIdx.x; i < NT*Dq; i += blockDim.x) {
        int u = i >> 6, d = i & 63;
        int row = g_top[bh*NT + u];
        O[((size_t)bh*Lq + row)*Dq + d] = g_ctx[(bh*NT + u)*Dq + d];
    }
}

extern "C" void kernel_launch(void* const* d_in, const int* in_sizes, int n_in,
                              void* d_out, int out_size) {
    const float* Q = (const float*)d_in[0];
    const float* K = (const float*)d_in[1];
    const float* V = (const float*)d_in[2];
    const int*   I = (const int*)  d_in[3];
    float* O = (float*)d_out;

    k_M      <<<dim3(BH, Lq/8), 256>>>(Q, K, I);
    k_topk   <<<BH, 256>>>();
    k_attn   <<<dim3(BH, NT), 256>>>(Q, K, V);
    k_csum1  <<<dim3(BH, NCH), 64>>>(V);
    k_csum2  <<<8, 256>>>();
    k_csum3  <<<dim3(BH, NCH), 64>>>(V, O);
    k_scatter<<<BH, 256>>>(O);
}